// round 15
// baseline (speedup 1.0000x reference)
#include <cuda_runtime.h>
#include <cuda_bf16.h>
#include <math_constants.h>
#include <stdint.h>

#define B_      4
#define N_      16384
#define STRIDE_ 4
#define K_      20
#define K2_     32          // screening candidate count
#define D_      64
#define DK_     67
#define KFS_    68
#define M_      4096
#define NQ_     (B_*M_)     // 16384
#define HID_    128
#define OUT_    128
#define TK_     128         // keys per tile
#define QB_     64          // queries per block (8 warps x 8)
#define ROW2_   28          // uints/row: [0..8] int8 dims0-35, [9..11] pad, [12..27] bf16x2 dims36-67

// scratch (no cudaMalloc allowed)
__device__ float    g_kf[(size_t)B_*N_*KFS_];   // fp32 features (pad=0) for exact rerank
__device__ uint32_t g_kfq[(size_t)B_*N_*ROW2_]; // mixed int8+bf16 screening rows
__device__ float    g_kn[B_*N_];                // key squared norms (fp32)
__device__ float    g_ksc[B_*N_];               // per-row quant scale (dims 0-35)
__device__ int      g_cand[NQ_*K2_];            // screening candidates
__device__ int      g_nbr[NQ_*K_];              // exact neighbor indices

static __device__ __forceinline__ uint32_t bf2_(float lo, float hi) {
    uint32_t r; asm("cvt.rn.bf16x2.f32 %0,%1,%2;" : "=r"(r) : "f"(hi), "f"(lo)); return r;
}
static __device__ __forceinline__ uint32_t hfma2_(uint32_t a, uint32_t b, uint32_t c) {
    uint32_t d; asm("fma.rn.bf16x2 %0,%1,%2,%3;" : "=r"(d) : "r"(a), "r"(b), "r"(c)); return d;
}
static __device__ __forceinline__ float hsum2_(uint32_t v) {
    __nv_bfloat162 h = *reinterpret_cast<__nv_bfloat162*>(&v);
    float2 f = __bfloat1622float2(h);
    return f.x + f.y;
}
// monotone float -> uint key (handles negatives); inverse
static __device__ __forceinline__ uint32_t fkey_(float x) {
    uint32_t u = __float_as_uint(x);
    return u ^ (uint32_t)(((int)u >> 31) | 0x80000000);
}
static __device__ __forceinline__ float funkey_(uint32_t k) {
    uint32_t u = (k & 0x80000000u) ? (k ^ 0x80000000u) : ~k;
    return __uint_as_float(u);
}
static __device__ __forceinline__ uint32_t redux_max_(uint32_t v) {
    uint32_t r; asm("redux.sync.max.u32 %0,%1,0xffffffff;" : "=r"(r) : "r"(v)); return r;
}

// ---------------------------------------------------------------------------
// Kernel 1: transform -> kf (fp32 + mixed int8/bf16 row), norms, scale,
// passthrough outputs
// ---------------------------------------------------------------------------
__global__ void __launch_bounds__(256) k_prep(const float* __restrict__ x,
                                              const float* __restrict__ pos,
                                              const float* __restrict__ lfr,
                                              float* __restrict__ outp,
                                              int out_size)
{
    int n = blockIdx.x * blockDim.x + threadIdx.x;
    if (n >= B_*N_) return;
    const float* xr = x + (size_t)n * D_;
    const float* R  = lfr + (size_t)n * 9;
    float r[9];
#pragma unroll
    for (int i = 0; i < 9; i++) r[i] = R[i];

    float kf[KFS_];
#pragma unroll
    for (int i = 0; i < 16; i++) kf[i] = xr[i];
#pragma unroll
    for (int v = 0; v < 16; v++) {
        float b0 = xr[16+3*v+0], b1 = xr[16+3*v+1], b2 = xr[16+3*v+2];
#pragma unroll
        for (int a = 0; a < 3; a++)
            kf[16+3*v+a] = r[0*3+a]*b0 + r[1*3+a]*b1 + r[2*3+a]*b2;
    }
    float p0 = pos[n*3+0], p1 = pos[n*3+1], p2 = pos[n*3+2];
    kf[64] = p0; kf[65] = p1; kf[66] = p2; kf[67] = 0.f;

    float s = 0.f, mx36 = 1e-20f;
#pragma unroll
    for (int i = 0; i < KFS_; i++) {
        g_kf[(size_t)n*KFS_ + i] = kf[i];
        s += kf[i]*kf[i];
        if (i < 36) mx36 = fmaxf(mx36, fabsf(kf[i]));
    }
    g_kn[n] = s;

    // dims 0..35: int8 (per-row scale over those dims); dims 36..67: bf16x2
    const float inv = 127.f / mx36;
    g_ksc[n] = mx36 * (1.f/127.f);
    uint32_t* qr = g_kfq + (size_t)n*ROW2_;
#pragma unroll
    for (int g = 0; g < 9; g++) {
        int a0 = __float2int_rn(kf[4*g+0]*inv);
        int a1 = __float2int_rn(kf[4*g+1]*inv);
        int a2 = __float2int_rn(kf[4*g+2]*inv);
        int a3 = __float2int_rn(kf[4*g+3]*inv);
        qr[g] = (uint32_t)(a0 & 0xff) | ((uint32_t)(a1 & 0xff) << 8)
              | ((uint32_t)(a2 & 0xff) << 16) | ((uint32_t)a3 << 24);
    }
    qr[9] = 0u; qr[10] = 0u; qr[11] = 0u;
#pragma unroll
    for (int i = 0; i < 16; i++)
        qr[12 + i] = bf2_(kf[36 + 2*i], kf[36 + 2*i + 1]);

    if ((n & 3) == 0) {
        int b   = n >> 14;
        int qid = b*M_ + ((n & (N_-1)) >> 2);
        const int off_pos = NQ_*OUT_;
        const int off_bat = off_pos + NQ_*3;
        const int off_lf  = off_bat + NQ_;
        if (out_size >= off_lf + NQ_*9) {
            float* pos_out = outp + off_pos;
            float* bat_out = outp + off_bat;
            float* lf_out  = outp + off_lf;
            pos_out[qid*3+0] = p0; pos_out[qid*3+1] = p1; pos_out[qid*3+2] = p2;
            bat_out[qid] = (float)b;
#pragma unroll
            for (int i = 0; i < 9; i++) lf_out[qid*9+i] = r[i];
        }
    }
}

// ---------------------------------------------------------------------------
// Warp-distributed top-32 insert — redux.sync based (proven)
// ---------------------------------------------------------------------------
__device__ __forceinline__ void topk_insert(float d2, int gidx,
                                            uint32_t& kdk, int& ki, float& th, int lane)
{
    unsigned m = __ballot_sync(0xffffffffu, d2 < th);
    while (m) {
        int src = __ffs(m) - 1; m &= m - 1;
        float v  = __shfl_sync(0xffffffffu, d2,  src);
        int   vi = __shfl_sync(0xffffffffu, gidx, src);
        if (v < th) {
            uint32_t mx = redux_max_(kdk);
            unsigned vict = __ballot_sync(0xffffffffu, kdk == mx);
            int ml = __ffs(vict) - 1;
            if (lane == ml) { kdk = fkey_(v); ki = vi; }
            th = funkey_(redux_max_(kdk));
        }
    }
}

// ---------------------------------------------------------------------------
// Kernel 2: mixed int8(dp4a)+bf16(hfma2) screening KNN -> top-32 per query.
// Dual-pipe: alu pipe does 9 dp4a/(q,k), fma pipe 16 hfma2/(q,k).
// Key tiles [128][28 words] double-buffered (7 chunks/row, conflict-free).
// ---------------------------------------------------------------------------
__global__ void __launch_bounds__(256) k_knn_mx()
{
    extern __shared__ uint32_t sh[];
    uint32_t* skq  = sh;                              // [QB_][28]
    uint32_t* skey = sh + QB_*ROW2_;                  // [2][TK_][28]
    float*    skn  = (float*)(sh + QB_*ROW2_ + 2*TK_*ROW2_);          // [2][TK_]
    float*    ssc  = (float*)(sh + QB_*ROW2_ + 2*TK_*ROW2_ + 2*TK_);  // [2][TK_]

    const int tid = threadIdx.x, lane = tid & 31, w = tid >> 5;
    const int qbase = blockIdx.x * QB_;
    const int b = qbase >> 12;
    const int kb0 = b * N_;

    // stage 64 query rows (7 uint4 chunks each)
    for (int i = tid; i < QB_*7; i += 256) {
        int row = i / 7, g = i - row*7;
        int pt = kb0 + ((qbase + row) - b*M_) * STRIDE_;
        *(uint4*)(skq + row*ROW2_ + 4*g) = *(const uint4*)(g_kfq + (size_t)pt*ROW2_ + 4*g);
    }
    // stage tile 0
    for (int i = tid; i < TK_*7; i += 256) {
        int row = i / 7, g = i - row*7;
        *(uint4*)(skey + row*ROW2_ + 4*g) = *(const uint4*)(g_kfq + (size_t)(kb0 + row)*ROW2_ + 4*g);
    }
    if (tid < TK_) { skn[tid] = g_kn[kb0 + tid]; ssc[tid] = g_ksc[kb0 + tid]; }

    float sq[8];
#pragma unroll
    for (int j = 0; j < 8; j++)
        sq[j] = g_ksc[kb0 + ((qbase + w*8 + j) - b*M_) * STRIDE_];

    uint32_t kdk[8];
    float th[8];
    int   ki[8];
    const uint32_t KINF = fkey_(CUDART_INF_F);
#pragma unroll
    for (int j = 0; j < 8; j++) { kdk[j] = KINF; ki[j] = 0; th[j] = CUDART_INF_F; }
    const uint32_t* qb = skq + (w*8)*ROW2_;

    __syncthreads();

    for (int t = 0; t < N_/TK_; t++) {
        const int buf = t & 1;
        if (t + 1 < N_/TK_) {
            uint32_t* dst = skey + (buf^1)*TK_*ROW2_;
            const uint32_t* src = g_kfq + (size_t)(kb0 + (t+1)*TK_)*ROW2_;
            for (int i = tid; i < TK_*7; i += 256) {
                int row = i / 7, g = i - row*7;
                *(uint4*)(dst + row*ROW2_ + 4*g) = *(const uint4*)(src + (size_t)row*ROW2_ + 4*g);
            }
            if (tid < TK_) {
                skn[(buf^1)*TK_ + tid] = g_kn[kb0 + (t+1)*TK_ + tid];
                ssc[(buf^1)*TK_ + tid] = g_ksc[kb0 + (t+1)*TK_ + tid];
            }
        }

        const uint32_t* kb = skey + buf*TK_*ROW2_;
        int      acci[8][4];
        uint32_t accf[8][4];
#pragma unroll
        for (int q = 0; q < 8; q++) {
            acci[q][0]=0;  acci[q][1]=0;  acci[q][2]=0;  acci[q][3]=0;
            accf[q][0]=0u; accf[q][1]=0u; accf[q][2]=0u; accf[q][3]=0u;
        }

        // ---- int8 part: words 0..7 (2 uint4 chunks) ----
#pragma unroll
        for (int g = 0; g < 2; g++) {
            uint4 k0 = *(const uint4*)(kb + (lane     )*ROW2_ + 4*g);
            uint4 k1 = *(const uint4*)(kb + (lane + 32)*ROW2_ + 4*g);
            uint4 k2 = *(const uint4*)(kb + (lane + 64)*ROW2_ + 4*g);
            uint4 k3 = *(const uint4*)(kb + (lane + 96)*ROW2_ + 4*g);
#pragma unroll
            for (int q = 0; q < 8; q++) {
                uint4 qv = *(const uint4*)(qb + q*ROW2_ + 4*g);
                acci[q][0] = __dp4a((int)qv.x, (int)k0.x, acci[q][0]);
                acci[q][1] = __dp4a((int)qv.x, (int)k1.x, acci[q][1]);
                acci[q][2] = __dp4a((int)qv.x, (int)k2.x, acci[q][2]);
                acci[q][3] = __dp4a((int)qv.x, (int)k3.x, acci[q][3]);
                acci[q][0] = __dp4a((int)qv.y, (int)k0.y, acci[q][0]);
                acci[q][1] = __dp4a((int)qv.y, (int)k1.y, acci[q][1]);
                acci[q][2] = __dp4a((int)qv.y, (int)k2.y, acci[q][2]);
                acci[q][3] = __dp4a((int)qv.y, (int)k3.y, acci[q][3]);
                acci[q][0] = __dp4a((int)qv.z, (int)k0.z, acci[q][0]);
                acci[q][1] = __dp4a((int)qv.z, (int)k1.z, acci[q][1]);
                acci[q][2] = __dp4a((int)qv.z, (int)k2.z, acci[q][2]);
                acci[q][3] = __dp4a((int)qv.z, (int)k3.z, acci[q][3]);
                acci[q][0] = __dp4a((int)qv.w, (int)k0.w, acci[q][0]);
                acci[q][1] = __dp4a((int)qv.w, (int)k1.w, acci[q][1]);
                acci[q][2] = __dp4a((int)qv.w, (int)k2.w, acci[q][2]);
                acci[q][3] = __dp4a((int)qv.w, (int)k3.w, acci[q][3]);
            }
        }
        // ---- int8 word 8 ----
        {
            int k0 = (int)kb[(lane     )*ROW2_ + 8];
            int k1 = (int)kb[(lane + 32)*ROW2_ + 8];
            int k2 = (int)kb[(lane + 64)*ROW2_ + 8];
            int k3 = (int)kb[(lane + 96)*ROW2_ + 8];
#pragma unroll
            for (int q = 0; q < 8; q++) {
                int qs = (int)qb[q*ROW2_ + 8];
                acci[q][0] = __dp4a(qs, k0, acci[q][0]);
                acci[q][1] = __dp4a(qs, k1, acci[q][1]);
                acci[q][2] = __dp4a(qs, k2, acci[q][2]);
                acci[q][3] = __dp4a(qs, k3, acci[q][3]);
            }
        }
        // ---- bf16 part: words 12..27 (4 uint4 chunks) ----
#pragma unroll
        for (int g = 0; g < 4; g++) {
            uint4 k0 = *(const uint4*)(kb + (lane     )*ROW2_ + 12 + 4*g);
            uint4 k1 = *(const uint4*)(kb + (lane + 32)*ROW2_ + 12 + 4*g);
            uint4 k2 = *(const uint4*)(kb + (lane + 64)*ROW2_ + 12 + 4*g);
            uint4 k3 = *(const uint4*)(kb + (lane + 96)*ROW2_ + 12 + 4*g);
#pragma unroll
            for (int q = 0; q < 8; q++) {
                uint4 qv = *(const uint4*)(qb + q*ROW2_ + 12 + 4*g);
                accf[q][0] = hfma2_(qv.x, k0.x, accf[q][0]);
                accf[q][1] = hfma2_(qv.x, k1.x, accf[q][1]);
                accf[q][2] = hfma2_(qv.x, k2.x, accf[q][2]);
                accf[q][3] = hfma2_(qv.x, k3.x, accf[q][3]);
                accf[q][0] = hfma2_(qv.y, k0.y, accf[q][0]);
                accf[q][1] = hfma2_(qv.y, k1.y, accf[q][1]);
                accf[q][2] = hfma2_(qv.y, k2.y, accf[q][2]);
                accf[q][3] = hfma2_(qv.y, k3.y, accf[q][3]);
                accf[q][0] = hfma2_(qv.z, k0.z, accf[q][0]);
                accf[q][1] = hfma2_(qv.z, k1.z, accf[q][1]);
                accf[q][2] = hfma2_(qv.z, k2.z, accf[q][2]);
                accf[q][3] = hfma2_(qv.z, k3.z, accf[q][3]);
                accf[q][0] = hfma2_(qv.w, k0.w, accf[q][0]);
                accf[q][1] = hfma2_(qv.w, k1.w, accf[q][1]);
                accf[q][2] = hfma2_(qv.w, k2.w, accf[q][2]);
                accf[q][3] = hfma2_(qv.w, k3.w, accf[q][3]);
            }
        }

        const float* knb = skn + buf*TK_;
        const float* scb = ssc + buf*TK_;
        const float kn0 = knb[lane], kn1 = knb[lane+32], kn2 = knb[lane+64], kn3 = knb[lane+96];
        const float c0 = -2.f*scb[lane],    c1 = -2.f*scb[lane+32];
        const float c2 = -2.f*scb[lane+64], c3 = -2.f*scb[lane+96];
        const int gi = kb0 + t*TK_ + lane;
#pragma unroll
        for (int q = 0; q < 8; q++) {
            float d20 = fmaf((float)acci[q][0], sq[q]*c0, fmaf(hsum2_(accf[q][0]), -2.f, kn0));
            float d21 = fmaf((float)acci[q][1], sq[q]*c1, fmaf(hsum2_(accf[q][1]), -2.f, kn1));
            float d22 = fmaf((float)acci[q][2], sq[q]*c2, fmaf(hsum2_(accf[q][2]), -2.f, kn2));
            float d23 = fmaf((float)acci[q][3], sq[q]*c3, fmaf(hsum2_(accf[q][3]), -2.f, kn3));
            float mn = fminf(fminf(d20, d21), fminf(d22, d23));
            if (__ballot_sync(0xffffffffu, mn < th[q])) {
                topk_insert(d20, gi,    kdk[q], ki[q], th[q], lane);
                topk_insert(d21, gi+32, kdk[q], ki[q], th[q], lane);
                topk_insert(d22, gi+64, kdk[q], ki[q], th[q], lane);
                topk_insert(d23, gi+96, kdk[q], ki[q], th[q], lane);
            }
        }
        __syncthreads();
    }

#pragma unroll
    for (int q = 0; q < 8; q++)
        g_cand[(size_t)(qbase + w*8 + q)*K2_ + lane] = ki[q];
}

// ---------------------------------------------------------------------------
// Kernel 2b: exact fp32 re-rank of 32 candidates -> top-20 set.
// ---------------------------------------------------------------------------
__global__ void __launch_bounds__(256) k_rerank()
{
    const int tid = threadIdx.x, lane = tid & 31, w = tid >> 5;
    const int q = blockIdx.x * 8 + w;
    const int b = q >> 12;
    const int pt = b*N_ + (q - b*M_) * STRIDE_;

    const int cand = g_cand[(size_t)q*K2_ + lane];
    const float4* qr = (const float4*)(g_kf + (size_t)pt*KFS_);
    const float4* kr = (const float4*)(g_kf + (size_t)cand*KFS_);
    float dot = 0.f;
#pragma unroll
    for (int g = 0; g < 17; g++) {
        float4 a = qr[g], c = kr[g];
        dot = fmaf(a.x,c.x, fmaf(a.y,c.y, fmaf(a.z,c.z, fmaf(a.w,c.w, dot))));
    }
    float d2 = g_kn[cand] - 2.f*dot;

#pragma unroll
    for (int r = 0; r < K_; r++) {
        float mv = d2; int ml = lane;
#pragma unroll
        for (int off = 16; off; off >>= 1) {
            float om = __shfl_xor_sync(0xffffffffu, mv, off);
            int   ol = __shfl_xor_sync(0xffffffffu, ml, off);
            if (om < mv || (om == mv && ol < ml)) { mv = om; ml = ol; }
        }
        if (lane == ml) { g_nbr[q*K_ + r] = cand; d2 = CUDART_INF_F; }
    }
}

// ---------------------------------------------------------------------------
// Kernel 3: edge MLP + maxpool — R14 (8 edges per weight pass, proven)
// ---------------------------------------------------------------------------
__global__ void __launch_bounds__(128, 6) k_mlp(const float* __restrict__ x,
                                                const float* __restrict__ lfr,
                                                const float* __restrict__ W1,
                                                const float* __restrict__ b1,
                                                const float* __restrict__ W2,
                                                const float* __restrict__ b2,
                                                float* __restrict__ outp)
{
    __shared__ __align__(16) float sxd[4][D_];
    __shared__ float slf[4][12];
    __shared__ __align__(16) float srel[4][8][D_];
    __shared__ __align__(16) float srl[4][8][D_];
    __shared__ __align__(16) float sa1[4][8][HID_];

    const int tid = threadIdx.x, lane = tid & 31, w = tid >> 5;
    const int q  = blockIdx.x * 4 + w;
    const int b  = q >> 12;
    const int pt = b*N_ + (q - b*M_) * STRIDE_;

    for (int d = lane; d < D_; d += 32) sxd[w][d] = x[(size_t)pt*D_ + d];
    if (lane < 9) slf[w][lane] = lfr[(size_t)pt*9 + lane];
    __syncwarp();

    const int c4 = lane * 4;
    float4 base = *(const float4*)(b1 + c4);
#pragma unroll 8
    for (int d = 0; d < D_; d++) {
        float xv = sxd[w][d];
        float4 w4 = __ldg((const float4*)(W1 + d*HID_ + c4));
        base.x += xv*w4.x; base.y += xv*w4.y; base.z += xv*w4.z; base.w += xv*w4.w;
    }
    const float4 b2v = __ldg((const float4*)(b2 + c4));
    float4 mx = make_float4(-CUDART_INF_F, -CUDART_INF_F, -CUDART_INF_F, -CUDART_INF_F);

    for (int grp = 0; grp < 3; grp++) {
        __syncwarp();
        int s = 0;
        if (lane < 8) {
            int ei = grp*8 + lane;
            if (ei > K_-1) ei = K_-1;            // pad with duplicates (max-pool safe)
            s = g_nbr[q*K_ + ei];
        }
        int ss[8];
#pragma unroll
        for (int e = 0; e < 8; e++) ss[e] = __shfl_sync(0xffffffffu, s, e);

#pragma unroll
        for (int e = 0; e < 8; e++) {
            const float* xs = x + (size_t)ss[e] * D_;
#pragma unroll
            for (int d = lane; d < D_; d += 32)
                srel[w][e][d] = xs[d] - sxd[w][d];
        }
        __syncwarp();
#pragma unroll
        for (int t = 0; t < 16; t++) {
            int item = lane + 32*t;
            int e = item >> 6;
            int d = item & 63;
            float v;
            if (d < 16) v = srel[w][e][d];
            else {
                int dd = d - 16;
                int a  = dd % 3;
                int vb = 16 + dd - a;
                v = slf[w][a*3+0]*srel[w][e][vb]
                  + slf[w][a*3+1]*srel[w][e][vb+1]
                  + slf[w][a*3+2]*srel[w][e][vb+2];
            }
            srl[w][e][d] = v;
        }
        __syncwarp();

        float4 ac[8];
#pragma unroll
        for (int e = 0; e < 8; e++) ac[e] = make_float4(0.f, 0.f, 0.f, 0.f);
#pragma unroll 1
        for (int d = 0; d < D_; d += 4) {
            float4 rv[8];
#pragma unroll
            for (int e = 0; e < 8; e++) rv[e] = *(const float4*)&srl[w][e][d];
#pragma unroll
            for (int dd = 0; dd < 4; dd++) {
                float4 w4 = __ldg((const float4*)(W1 + (D_+d+dd)*HID_ + c4));
#pragma unroll
                for (int e = 0; e < 8; e++) {
                    float a = (&rv[e].x)[dd];
                    ac[e].x += a*w4.x; ac[e].y += a*w4.y; ac[e].z += a*w4.z; ac[e].w += a*w4.w;
                }
            }
        }
#pragma unroll
        for (int e = 0; e < 8; e++) {
            float4 a;
            a.x = fmaxf(base.x + ac[e].x, 0.f);
            a.y = fmaxf(base.y + ac[e].y, 0.f);
            a.z = fmaxf(base.z + ac[e].z, 0.f);
            a.w = fmaxf(base.w + ac[e].w, 0.f);
            *(float4*)&sa1[w][e][c4] = a;
        }
        __syncwarp();

        float4 m[8];
#pragma unroll
        for (int e = 0; e < 8; e++) m[e] = b2v;
#pragma unroll 1
        for (int j = 0; j < HID_; j += 4) {
            float4 av[8];
#pragma unroll
            for (int e = 0; e < 8; e++) av[e] = *(const float4*)&sa1[w][e][j];
#pragma unroll
            for (int jj = 0; jj < 4; jj++) {
                float4 w4 = __ldg((const float4*)(W2 + (j+jj)*HID_ + c4));
#pragma unroll
                for (int e = 0; e < 8; e++) {
                    float a = (&av[e].x)[jj];
                    m[e].x += a*w4.x; m[e].y += a*w4.y; m[e].z += a*w4.z; m[e].w += a*w4.w;
                }
            }
        }
#pragma unroll
        for (int e = 0; e < 8; e++) {
            mx.x = fmaxf(mx.x, m[e].x);
            mx.y = fmaxf(mx.y, m[e].y);
            mx.z = fmaxf(mx.z, m[e].z);
            mx.w = fmaxf(mx.w, m[e].w);
        }
    }

    *(float4*)(outp + (size_t)q*OUT_ + c4) = mx;
}

// ---------------------------------------------------------------------------
extern "C" void kernel_launch(void* const* d_in, const int* in_sizes, int n_in,
                              void* d_out, int out_size)
{
    const float* x   = (const float*)d_in[0];
    const float* pos = (const float*)d_in[1];
    const float* lfr = (const float*)d_in[2];
    const float* W1  = (const float*)d_in[4];
    const float* b1  = (const float*)d_in[5];
    const float* W2  = (const float*)d_in[6];
    const float* b2  = (const float*)d_in[7];
    float* outp = (float*)d_out;

    const int knn_smem = (QB_*ROW2_ + 2*TK_*ROW2_ + 2*TK_ + 2*TK_) * 4; // 37888 B
    cudaFuncSetAttribute(k_knn_mx, cudaFuncAttributeMaxDynamicSharedMemorySize, knn_smem);

    k_prep<<<(B_*N_ + 255)/256, 256>>>(x, pos, lfr, outp, out_size);
    k_knn_mx<<<NQ_/QB_, 256, knn_smem>>>();
    k_rerank<<<NQ_/8, 256>>>();
    k_mlp<<<NQ_/4, 128>>>(x, lfr, W1, b1, W2, b2, outp);
}

// round 16
// speedup vs baseline: 1.2794x; 1.2794x over previous
#include <cuda_runtime.h>
#include <cuda_bf16.h>
#include <math_constants.h>
#include <stdint.h>

#define B_      4
#define N_      16384
#define STRIDE_ 4
#define K_      20
#define K2_     32          // screening candidate count
#define D_      64
#define DK_     67
#define KFS_    68
#define M_      4096
#define NQ_     (B_*M_)     // 16384
#define HID_    128
#define OUT_    128
#define TK_     128         // keys per tile
#define QB_     32          // queries per block (8 warps x 4)
#define QW_     4           // queries per warp
#define ROW2_   28          // uints/row: [0..8] int8 dims0-35, [9..11] pad, [12..27] bf16x2 dims36-67

// scratch (no cudaMalloc allowed)
__device__ float    g_kf[(size_t)B_*N_*KFS_];   // fp32 features (pad=0) for exact rerank
__device__ uint32_t g_kfq[(size_t)B_*N_*ROW2_]; // mixed int8+bf16 screening rows
__device__ float    g_kn[B_*N_];                // key squared norms (fp32)
__device__ float    g_ksc[B_*N_];               // per-row quant scale (dims 0-35)
__device__ int      g_cand[NQ_*K2_];            // screening candidates
__device__ int      g_nbr[NQ_*K_];              // exact neighbor indices

static __device__ __forceinline__ uint32_t bf2_(float lo, float hi) {
    uint32_t r; asm("cvt.rn.bf16x2.f32 %0,%1,%2;" : "=r"(r) : "f"(hi), "f"(lo)); return r;
}
static __device__ __forceinline__ uint32_t hfma2_(uint32_t a, uint32_t b, uint32_t c) {
    uint32_t d; asm("fma.rn.bf16x2 %0,%1,%2,%3;" : "=r"(d) : "r"(a), "r"(b), "r"(c)); return d;
}
static __device__ __forceinline__ float hsum2_(uint32_t v) {
    __nv_bfloat162 h = *reinterpret_cast<__nv_bfloat162*>(&v);
    float2 f = __bfloat1622float2(h);
    return f.x + f.y;
}
// monotone float -> uint key (handles negatives); inverse
static __device__ __forceinline__ uint32_t fkey_(float x) {
    uint32_t u = __float_as_uint(x);
    return u ^ (uint32_t)(((int)u >> 31) | 0x80000000);
}
static __device__ __forceinline__ float funkey_(uint32_t k) {
    uint32_t u = (k & 0x80000000u) ? (k ^ 0x80000000u) : ~k;
    return __uint_as_float(u);
}
static __device__ __forceinline__ uint32_t redux_max_(uint32_t v) {
    uint32_t r; asm("redux.sync.max.u32 %0,%1,0xffffffff;" : "=r"(r) : "r"(v)); return r;
}

// ---------------------------------------------------------------------------
// Kernel 1: transform -> kf (fp32 + mixed int8/bf16 row), norms, scale,
// passthrough outputs (identical to R15 — numerics validated)
// ---------------------------------------------------------------------------
__global__ void __launch_bounds__(256) k_prep(const float* __restrict__ x,
                                              const float* __restrict__ pos,
                                              const float* __restrict__ lfr,
                                              float* __restrict__ outp,
                                              int out_size)
{
    int n = blockIdx.x * blockDim.x + threadIdx.x;
    if (n >= B_*N_) return;
    const float* xr = x + (size_t)n * D_;
    const float* R  = lfr + (size_t)n * 9;
    float r[9];
#pragma unroll
    for (int i = 0; i < 9; i++) r[i] = R[i];

    float kf[KFS_];
#pragma unroll
    for (int i = 0; i < 16; i++) kf[i] = xr[i];
#pragma unroll
    for (int v = 0; v < 16; v++) {
        float b0 = xr[16+3*v+0], b1 = xr[16+3*v+1], b2 = xr[16+3*v+2];
#pragma unroll
        for (int a = 0; a < 3; a++)
            kf[16+3*v+a] = r[0*3+a]*b0 + r[1*3+a]*b1 + r[2*3+a]*b2;
    }
    float p0 = pos[n*3+0], p1 = pos[n*3+1], p2 = pos[n*3+2];
    kf[64] = p0; kf[65] = p1; kf[66] = p2; kf[67] = 0.f;

    float s = 0.f, mx36 = 1e-20f;
#pragma unroll
    for (int i = 0; i < KFS_; i++) {
        g_kf[(size_t)n*KFS_ + i] = kf[i];
        s += kf[i]*kf[i];
        if (i < 36) mx36 = fmaxf(mx36, fabsf(kf[i]));
    }
    g_kn[n] = s;

    const float inv = 127.f / mx36;
    g_ksc[n] = mx36 * (1.f/127.f);
    uint32_t* qr = g_kfq + (size_t)n*ROW2_;
#pragma unroll
    for (int g = 0; g < 9; g++) {
        int a0 = __float2int_rn(kf[4*g+0]*inv);
        int a1 = __float2int_rn(kf[4*g+1]*inv);
        int a2 = __float2int_rn(kf[4*g+2]*inv);
        int a3 = __float2int_rn(kf[4*g+3]*inv);
        qr[g] = (uint32_t)(a0 & 0xff) | ((uint32_t)(a1 & 0xff) << 8)
              | ((uint32_t)(a2 & 0xff) << 16) | ((uint32_t)a3 << 24);
    }
    qr[9] = 0u; qr[10] = 0u; qr[11] = 0u;
#pragma unroll
    for (int i = 0; i < 16; i++)
        qr[12 + i] = bf2_(kf[36 + 2*i], kf[36 + 2*i + 1]);

    if ((n & 3) == 0) {
        int b   = n >> 14;
        int qid = b*M_ + ((n & (N_-1)) >> 2);
        const int off_pos = NQ_*OUT_;
        const int off_bat = off_pos + NQ_*3;
        const int off_lf  = off_bat + NQ_;
        if (out_size >= off_lf + NQ_*9) {
            float* pos_out = outp + off_pos;
            float* bat_out = outp + off_bat;
            float* lf_out  = outp + off_lf;
            pos_out[qid*3+0] = p0; pos_out[qid*3+1] = p1; pos_out[qid*3+2] = p2;
            bat_out[qid] = (float)b;
#pragma unroll
            for (int i = 0; i < 9; i++) lf_out[qid*9+i] = r[i];
        }
    }
}

// ---------------------------------------------------------------------------
// Warp-distributed top-32 insert — redux.sync based (proven)
// ---------------------------------------------------------------------------
__device__ __forceinline__ void topk_insert(float d2, int gidx,
                                            uint32_t& kdk, int& ki, float& th, int lane)
{
    unsigned m = __ballot_sync(0xffffffffu, d2 < th);
    while (m) {
        int src = __ffs(m) - 1; m &= m - 1;
        float v  = __shfl_sync(0xffffffffu, d2,  src);
        int   vi = __shfl_sync(0xffffffffu, gidx, src);
        if (v < th) {
            uint32_t mx = redux_max_(kdk);
            unsigned vict = __ballot_sync(0xffffffffu, kdk == mx);
            int ml = __ffs(vict) - 1;
            if (lane == ml) { kdk = fkey_(v); ki = vi; }
            th = funkey_(redux_max_(kdk));
        }
    }
}

// ---------------------------------------------------------------------------
// Kernel 2: mixed int8(dp4a)+bf16(hfma2) screening, 4 queries/warp (low regs).
// Block = 256 thr = 8 warps = 32 queries. Key tiles double-buffered.
// ---------------------------------------------------------------------------
__global__ void __launch_bounds__(256, 3) k_knn_mx()
{
    extern __shared__ uint32_t sh[];
    uint32_t* skq  = sh;                              // [QB_][28]
    uint32_t* skey = sh + QB_*ROW2_;                  // [2][TK_][28]
    float*    skn  = (float*)(sh + QB_*ROW2_ + 2*TK_*ROW2_);          // [2][TK_]
    float*    ssc  = (float*)(sh + QB_*ROW2_ + 2*TK_*ROW2_ + 2*TK_);  // [2][TK_]

    const int tid = threadIdx.x, lane = tid & 31, w = tid >> 5;
    const int qbase = blockIdx.x * QB_;
    const int b = qbase >> 12;
    const int kb0 = b * N_;

    // stage 32 query rows (7 uint4 chunks each)
    for (int i = tid; i < QB_*7; i += 256) {
        int row = i / 7, g = i - row*7;
        int pt = kb0 + ((qbase + row) - b*M_) * STRIDE_;
        *(uint4*)(skq + row*ROW2_ + 4*g) = *(const uint4*)(g_kfq + (size_t)pt*ROW2_ + 4*g);
    }
    // stage tile 0
    for (int i = tid; i < TK_*7; i += 256) {
        int row = i / 7, g = i - row*7;
        *(uint4*)(skey + row*ROW2_ + 4*g) = *(const uint4*)(g_kfq + (size_t)(kb0 + row)*ROW2_ + 4*g);
    }
    if (tid < TK_) { skn[tid] = g_kn[kb0 + tid]; ssc[tid] = g_ksc[kb0 + tid]; }

    float sq[QW_];
#pragma unroll
    for (int j = 0; j < QW_; j++)
        sq[j] = g_ksc[kb0 + ((qbase + w*QW_ + j) - b*M_) * STRIDE_];

    uint32_t kdk[QW_];
    float th[QW_];
    int   ki[QW_];
    const uint32_t KINF = fkey_(CUDART_INF_F);
#pragma unroll
    for (int j = 0; j < QW_; j++) { kdk[j] = KINF; ki[j] = 0; th[j] = CUDART_INF_F; }
    const uint32_t* qb = skq + (w*QW_)*ROW2_;

    __syncthreads();

    for (int t = 0; t < N_/TK_; t++) {
        const int buf = t & 1;
        if (t + 1 < N_/TK_) {
            uint32_t* dst = skey + (buf^1)*TK_*ROW2_;
            const uint32_t* src = g_kfq + (size_t)(kb0 + (t+1)*TK_)*ROW2_;
            for (int i = tid; i < TK_*7; i += 256) {
                int row = i / 7, g = i - row*7;
                *(uint4*)(dst + row*ROW2_ + 4*g) = *(const uint4*)(src + (size_t)row*ROW2_ + 4*g);
            }
            if (tid < TK_) {
                skn[(buf^1)*TK_ + tid] = g_kn[kb0 + (t+1)*TK_ + tid];
                ssc[(buf^1)*TK_ + tid] = g_ksc[kb0 + (t+1)*TK_ + tid];
            }
        }

        const uint32_t* kb = skey + buf*TK_*ROW2_;
        int      acci[QW_][4];
        uint32_t accf[QW_][4];
#pragma unroll
        for (int q = 0; q < QW_; q++) {
            acci[q][0]=0;  acci[q][1]=0;  acci[q][2]=0;  acci[q][3]=0;
            accf[q][0]=0u; accf[q][1]=0u; accf[q][2]=0u; accf[q][3]=0u;
        }

        // ---- int8 part: words 0..7 (2 uint4 chunks) ----
#pragma unroll
        for (int g = 0; g < 2; g++) {
            uint4 k0 = *(const uint4*)(kb + (lane     )*ROW2_ + 4*g);
            uint4 k1 = *(const uint4*)(kb + (lane + 32)*ROW2_ + 4*g);
            uint4 k2 = *(const uint4*)(kb + (lane + 64)*ROW2_ + 4*g);
            uint4 k3 = *(const uint4*)(kb + (lane + 96)*ROW2_ + 4*g);
#pragma unroll
            for (int q = 0; q < QW_; q++) {
                uint4 qv = *(const uint4*)(qb + q*ROW2_ + 4*g);
                acci[q][0] = __dp4a((int)qv.x, (int)k0.x, acci[q][0]);
                acci[q][1] = __dp4a((int)qv.x, (int)k1.x, acci[q][1]);
                acci[q][2] = __dp4a((int)qv.x, (int)k2.x, acci[q][2]);
                acci[q][3] = __dp4a((int)qv.x, (int)k3.x, acci[q][3]);
                acci[q][0] = __dp4a((int)qv.y, (int)k0.y, acci[q][0]);
                acci[q][1] = __dp4a((int)qv.y, (int)k1.y, acci[q][1]);
                acci[q][2] = __dp4a((int)qv.y, (int)k2.y, acci[q][2]);
                acci[q][3] = __dp4a((int)qv.y, (int)k3.y, acci[q][3]);
                acci[q][0] = __dp4a((int)qv.z, (int)k0.z, acci[q][0]);
                acci[q][1] = __dp4a((int)qv.z, (int)k1.z, acci[q][1]);
                acci[q][2] = __dp4a((int)qv.z, (int)k2.z, acci[q][2]);
                acci[q][3] = __dp4a((int)qv.z, (int)k3.z, acci[q][3]);
                acci[q][0] = __dp4a((int)qv.w, (int)k0.w, acci[q][0]);
                acci[q][1] = __dp4a((int)qv.w, (int)k1.w, acci[q][1]);
                acci[q][2] = __dp4a((int)qv.w, (int)k2.w, acci[q][2]);
                acci[q][3] = __dp4a((int)qv.w, (int)k3.w, acci[q][3]);
            }
        }
        // ---- int8 word 8 ----
        {
            int k0 = (int)kb[(lane     )*ROW2_ + 8];
            int k1 = (int)kb[(lane + 32)*ROW2_ + 8];
            int k2 = (int)kb[(lane + 64)*ROW2_ + 8];
            int k3 = (int)kb[(lane + 96)*ROW2_ + 8];
#pragma unroll
            for (int q = 0; q < QW_; q++) {
                int qs = (int)qb[q*ROW2_ + 8];
                acci[q][0] = __dp4a(qs, k0, acci[q][0]);
                acci[q][1] = __dp4a(qs, k1, acci[q][1]);
                acci[q][2] = __dp4a(qs, k2, acci[q][2]);
                acci[q][3] = __dp4a(qs, k3, acci[q][3]);
            }
        }
        // ---- bf16 part: words 12..27 (4 uint4 chunks) ----
#pragma unroll
        for (int g = 0; g < 4; g++) {
            uint4 k0 = *(const uint4*)(kb + (lane     )*ROW2_ + 12 + 4*g);
            uint4 k1 = *(const uint4*)(kb + (lane + 32)*ROW2_ + 12 + 4*g);
            uint4 k2 = *(const uint4*)(kb + (lane + 64)*ROW2_ + 12 + 4*g);
            uint4 k3 = *(const uint4*)(kb + (lane + 96)*ROW2_ + 12 + 4*g);
#pragma unroll
            for (int q = 0; q < QW_; q++) {
                uint4 qv = *(const uint4*)(qb + q*ROW2_ + 12 + 4*g);
                accf[q][0] = hfma2_(qv.x, k0.x, accf[q][0]);
                accf[q][1] = hfma2_(qv.x, k1.x, accf[q][1]);
                accf[q][2] = hfma2_(qv.x, k2.x, accf[q][2]);
                accf[q][3] = hfma2_(qv.x, k3.x, accf[q][3]);
                accf[q][0] = hfma2_(qv.y, k0.y, accf[q][0]);
                accf[q][1] = hfma2_(qv.y, k1.y, accf[q][1]);
                accf[q][2] = hfma2_(qv.y, k2.y, accf[q][2]);
                accf[q][3] = hfma2_(qv.y, k3.y, accf[q][3]);
                accf[q][0] = hfma2_(qv.z, k0.z, accf[q][0]);
                accf[q][1] = hfma2_(qv.z, k1.z, accf[q][1]);
                accf[q][2] = hfma2_(qv.z, k2.z, accf[q][2]);
                accf[q][3] = hfma2_(qv.z, k3.z, accf[q][3]);
                accf[q][0] = hfma2_(qv.w, k0.w, accf[q][0]);
                accf[q][1] = hfma2_(qv.w, k1.w, accf[q][1]);
                accf[q][2] = hfma2_(qv.w, k2.w, accf[q][2]);
                accf[q][3] = hfma2_(qv.w, k3.w, accf[q][3]);
            }
        }

        const float* knb = skn + buf*TK_;
        const float* scb = ssc + buf*TK_;
        const float kn0 = knb[lane], kn1 = knb[lane+32], kn2 = knb[lane+64], kn3 = knb[lane+96];
        const float c0 = -2.f*scb[lane],    c1 = -2.f*scb[lane+32];
        const float c2 = -2.f*scb[lane+64], c3 = -2.f*scb[lane+96];
        const int gi = kb0 + t*TK_ + lane;
#pragma unroll
        for (int q = 0; q < QW_; q++) {
            float d20 = fmaf((float)acci[q][0], sq[q]*c0, fmaf(hsum2_(accf[q][0]), -2.f, kn0));
            float d21 = fmaf((float)acci[q][1], sq[q]*c1, fmaf(hsum2_(accf[q][1]), -2.f, kn1));
            float d22 = fmaf((float)acci[q][2], sq[q]*c2, fmaf(hsum2_(accf[q][2]), -2.f, kn2));
            float d23 = fmaf((float)acci[q][3], sq[q]*c3, fmaf(hsum2_(accf[q][3]), -2.f, kn3));
            float mn = fminf(fminf(d20, d21), fminf(d22, d23));
            if (__ballot_sync(0xffffffffu, mn < th[q])) {
                topk_insert(d20, gi,    kdk[q], ki[q], th[q], lane);
                topk_insert(d21, gi+32, kdk[q], ki[q], th[q], lane);
                topk_insert(d22, gi+64, kdk[q], ki[q], th[q], lane);
                topk_insert(d23, gi+96, kdk[q], ki[q], th[q], lane);
            }
        }
        __syncthreads();
    }

#pragma unroll
    for (int q = 0; q < QW_; q++)
        g_cand[(size_t)(qbase + w*QW_ + q)*K2_ + lane] = ki[q];
}

// ---------------------------------------------------------------------------
// Kernel 2b: exact fp32 re-rank of 32 candidates -> top-20 set.
// ---------------------------------------------------------------------------
__global__ void __launch_bounds__(256) k_rerank()
{
    const int tid = threadIdx.x, lane = tid & 31, w = tid >> 5;
    const int q = blockIdx.x * 8 + w;
    const int b = q >> 12;
    const int pt = b*N_ + (q - b*M_) * STRIDE_;

    const int cand = g_cand[(size_t)q*K2_ + lane];
    const float4* qr = (const float4*)(g_kf + (size_t)pt*KFS_);
    const float4* kr = (const float4*)(g_kf + (size_t)cand*KFS_);
    float dot = 0.f;
#pragma unroll
    for (int g = 0; g < 17; g++) {
        float4 a = qr[g], c = kr[g];
        dot = fmaf(a.x,c.x, fmaf(a.y,c.y, fmaf(a.z,c.z, fmaf(a.w,c.w, dot))));
    }
    float d2 = g_kn[cand] - 2.f*dot;

#pragma unroll
    for (int r = 0; r < K_; r++) {
        float mv = d2; int ml = lane;
#pragma unroll
        for (int off = 16; off; off >>= 1) {
            float om = __shfl_xor_sync(0xffffffffu, mv, off);
            int   ol = __shfl_xor_sync(0xffffffffu, ml, off);
            if (om < mv || (om == mv && ol < ml)) { mv = om; ml = ol; }
        }
        if (lane == ml) { g_nbr[q*K_ + r] = cand; d2 = CUDART_INF_F; }
    }
}

// ---------------------------------------------------------------------------
// Kernel 3: edge MLP + maxpool — R14 (8 edges per weight pass, proven)
// ---------------------------------------------------------------------------
__global__ void __launch_bounds__(128, 6) k_mlp(const float* __restrict__ x,
                                                const float* __restrict__ lfr,
                                                const float* __restrict__ W1,
                                                const float* __restrict__ b1,
                                                const float* __restrict__ W2,
                                                const float* __restrict__ b2,
                                                float* __restrict__ outp)
{
    __shared__ __align__(16) float sxd[4][D_];
    __shared__ float slf[4][12];
    __shared__ __align__(16) float srel[4][8][D_];
    __shared__ __align__(16) float srl[4][8][D_];
    __shared__ __align__(16) float sa1[4][8][HID_];

    const int tid = threadIdx.x, lane = tid & 31, w = tid >> 5;
    const int q  = blockIdx.x * 4 + w;
    const int b  = q >> 12;
    const int pt = b*N_ + (q - b*M_) * STRIDE_;

    for (int d = lane; d < D_; d += 32) sxd[w][d] = x[(size_t)pt*D_ + d];
    if (lane < 9) slf[w][lane] = lfr[(size_t)pt*9 + lane];
    __syncwarp();

    const int c4 = lane * 4;
    float4 base = *(const float4*)(b1 + c4);
#pragma unroll 8
    for (int d = 0; d < D_; d++) {
        float xv = sxd[w][d];
        float4 w4 = __ldg((const float4*)(W1 + d*HID_ + c4));
        base.x += xv*w4.x; base.y += xv*w4.y; base.z += xv*w4.z; base.w += xv*w4.w;
    }
    const float4 b2v = __ldg((const float4*)(b2 + c4));
    float4 mx = make_float4(-CUDART_INF_F, -CUDART_INF_F, -CUDART_INF_F, -CUDART_INF_F);

    for (int grp = 0; grp < 3; grp++) {
        __syncwarp();
        int s = 0;
        if (lane < 8) {
            int ei = grp*8 + lane;
            if (ei > K_-1) ei = K_-1;            // pad with duplicates (max-pool safe)
            s = g_nbr[q*K_ + ei];
        }
        int ss[8];
#pragma unroll
        for (int e = 0; e < 8; e++) ss[e] = __shfl_sync(0xffffffffu, s, e);

#pragma unroll
        for (int e = 0; e < 8; e++) {
            const float* xs = x + (size_t)ss[e] * D_;
#pragma unroll
            for (int d = lane; d < D_; d += 32)
                srel[w][e][d] = xs[d] - sxd[w][d];
        }
        __syncwarp();
#pragma unroll
        for (int t = 0; t < 16; t++) {
            int item = lane + 32*t;
            int e = item >> 6;
            int d = item & 63;
            float v;
            if (d < 16) v = srel[w][e][d];
            else {
                int dd = d - 16;
                int a  = dd % 3;
                int vb = 16 + dd - a;
                v = slf[w][a*3+0]*srel[w][e][vb]
                  + slf[w][a*3+1]*srel[w][e][vb+1]
                  + slf[w][a*3+2]*srel[w][e][vb+2];
            }
            srl[w][e][d] = v;
        }
        __syncwarp();

        float4 ac[8];
#pragma unroll
        for (int e = 0; e < 8; e++) ac[e] = make_float4(0.f, 0.f, 0.f, 0.f);
#pragma unroll 1
        for (int d = 0; d < D_; d += 4) {
            float4 rv[8];
#pragma unroll
            for (int e = 0; e < 8; e++) rv[e] = *(const float4*)&srl[w][e][d];
#pragma unroll
            for (int dd = 0; dd < 4; dd++) {
                float4 w4 = __ldg((const float4*)(W1 + (D_+d+dd)*HID_ + c4));
#pragma unroll
                for (int e = 0; e < 8; e++) {
                    float a = (&rv[e].x)[dd];
                    ac[e].x += a*w4.x; ac[e].y += a*w4.y; ac[e].z += a*w4.z; ac[e].w += a*w4.w;
                }
            }
        }
#pragma unroll
        for (int e = 0; e < 8; e++) {
            float4 a;
            a.x = fmaxf(base.x + ac[e].x, 0.f);
            a.y = fmaxf(base.y + ac[e].y, 0.f);
            a.z = fmaxf(base.z + ac[e].z, 0.f);
            a.w = fmaxf(base.w + ac[e].w, 0.f);
            *(float4*)&sa1[w][e][c4] = a;
        }
        __syncwarp();

        float4 m[8];
#pragma unroll
        for (int e = 0; e < 8; e++) m[e] = b2v;
#pragma unroll 1
        for (int j = 0; j < HID_; j += 4) {
            float4 av[8];
#pragma unroll
            for (int e = 0; e < 8; e++) av[e] = *(const float4*)&sa1[w][e][j];
#pragma unroll
            for (int jj = 0; jj < 4; jj++) {
                float4 w4 = __ldg((const float4*)(W2 + (j+jj)*HID_ + c4));
#pragma unroll
                for (int e = 0; e < 8; e++) {
                    float a = (&av[e].x)[jj];
                    m[e].x += a*w4.x; m[e].y += a*w4.y; m[e].z += a*w4.z; m[e].w += a*w4.w;
                }
            }
        }
#pragma unroll
        for (int e = 0; e < 8; e++) {
            mx.x = fmaxf(mx.x, m[e].x);
            mx.y = fmaxf(mx.y, m[e].y);
            mx.z = fmaxf(mx.z, m[e].z);
            mx.w = fmaxf(mx.w, m[e].w);
        }
    }

    *(float4*)(outp + (size_t)q*OUT_ + c4) = mx;
}

// ---------------------------------------------------------------------------
extern "C" void kernel_launch(void* const* d_in, const int* in_sizes, int n_in,
                              void* d_out, int out_size)
{
    const float* x   = (const float*)d_in[0];
    const float* pos = (const float*)d_in[1];
    const float* lfr = (const float*)d_in[2];
    const float* W1  = (const float*)d_in[4];
    const float* b1  = (const float*)d_in[5];
    const float* W2  = (const float*)d_in[6];
    const float* b2  = (const float*)d_in[7];
    float* outp = (float*)d_out;

    const int knn_smem = (QB_*ROW2_ + 2*TK_*ROW2_ + 2*TK_ + 2*TK_) * 4; // 34304 B
    cudaFuncSetAttribute(k_knn_mx, cudaFuncAttributeMaxDynamicSharedMemorySize, knn_smem);

    k_prep<<<(B_*N_ + 255)/256, 256>>>(x, pos, lfr, outp, out_size);
    k_knn_mx<<<NQ_/QB_, 256, knn_smem>>>();
    k_rerank<<<NQ_/8, 256>>>();
    k_mlp<<<NQ_/4, 128>>>(x, lfr, W1, b1, W2, b2, outp);
}

// round 17
// speedup vs baseline: 1.5290x; 1.1951x over previous
#include <cuda_runtime.h>
#include <math_constants.h>
#include <stdint.h>

#define B_      4
#define N_      16384
#define STRIDE_ 4
#define K_      20
#define K2_     32          // screening candidate count
#define D_      64
#define DK_     67
#define KFS_    68
#define M_      4096
#define NQ_     (B_*M_)     // 16384
#define HID_    128
#define OUT_    128
#define TK2_    256         // keys per buffered tile (2 halves of 128)
#define NT2_    (N_/TK2_)   // 64
#define QB_     64          // queries per block (8 warps x 8)
#define ROWQ_   20          // uints per int8 feature row (68 dims + 12 pad)

// scratch (no cudaMalloc allowed)
__device__ float    g_kf[(size_t)B_*N_*KFS_];   // fp32 features (pad=0) for exact rerank
__device__ uint32_t g_kfq[(size_t)B_*N_*ROWQ_]; // int8 features (pads=0) for screening
__device__ float    g_kn[B_*N_];                // key squared norms (fp32)
__device__ float    g_ksc[B_*N_];               // per-row quant scale
__device__ int      g_cand[NQ_*K2_];            // screening candidates
__device__ int      g_nbr[NQ_*K_];              // exact neighbor indices

// monotone float -> uint key (handles negatives); inverse
static __device__ __forceinline__ uint32_t fkey_(float x) {
    uint32_t u = __float_as_uint(x);
    return u ^ (uint32_t)(((int)u >> 31) | 0x80000000);
}
static __device__ __forceinline__ float funkey_(uint32_t k) {
    uint32_t u = (k & 0x80000000u) ? (k ^ 0x80000000u) : ~k;
    return __uint_as_float(u);
}
static __device__ __forceinline__ uint32_t redux_max_(uint32_t v) {
    uint32_t r; asm("redux.sync.max.u32 %0,%1,0xffffffff;" : "=r"(r) : "r"(v)); return r;
}

// ---------------------------------------------------------------------------
// Kernel 1: per-point transform -> kf (fp32 + int8), norms, scale, passthrough
// (byte-identical to R13/R14)
// ---------------------------------------------------------------------------
__global__ void __launch_bounds__(256) k_prep(const float* __restrict__ x,
                                              const float* __restrict__ pos,
                                              const float* __restrict__ lfr,
                                              float* __restrict__ outp,
                                              int out_size)
{
    int n = blockIdx.x * blockDim.x + threadIdx.x;
    if (n >= B_*N_) return;
    const float* xr = x + (size_t)n * D_;
    const float* R  = lfr + (size_t)n * 9;
    float r[9];
#pragma unroll
    for (int i = 0; i < 9; i++) r[i] = R[i];

    float kf[KFS_];
#pragma unroll
    for (int i = 0; i < 16; i++) kf[i] = xr[i];
#pragma unroll
    for (int v = 0; v < 16; v++) {
        float b0 = xr[16+3*v+0], b1 = xr[16+3*v+1], b2 = xr[16+3*v+2];
#pragma unroll
        for (int a = 0; a < 3; a++)
            kf[16+3*v+a] = r[0*3+a]*b0 + r[1*3+a]*b1 + r[2*3+a]*b2;
    }
    float p0 = pos[n*3+0], p1 = pos[n*3+1], p2 = pos[n*3+2];
    kf[64] = p0; kf[65] = p1; kf[66] = p2; kf[67] = 0.f;

    float s = 0.f, mxv = 1e-20f;
#pragma unroll
    for (int i = 0; i < KFS_; i++) {
        g_kf[(size_t)n*KFS_ + i] = kf[i];
        s += kf[i]*kf[i];
        mxv = fmaxf(mxv, fabsf(kf[i]));
    }
    g_kn[n] = s;

    const float inv = 127.f / mxv;
    g_ksc[n] = mxv * (1.f/127.f);
    uint32_t* qr = g_kfq + (size_t)n*ROWQ_;
#pragma unroll
    for (int g = 0; g < 17; g++) {
        int a0 = __float2int_rn(kf[4*g+0]*inv);
        int a1 = __float2int_rn(kf[4*g+1]*inv);
        int a2 = __float2int_rn(kf[4*g+2]*inv);
        int a3 = __float2int_rn(kf[4*g+3]*inv);
        qr[g] = (uint32_t)(a0 & 0xff) | ((uint32_t)(a1 & 0xff) << 8)
              | ((uint32_t)(a2 & 0xff) << 16) | ((uint32_t)a3 << 24);
    }
    qr[17] = 0u; qr[18] = 0u; qr[19] = 0u;

    if ((n & 3) == 0) {
        int b   = n >> 14;
        int qid = b*M_ + ((n & (N_-1)) >> 2);
        const int off_pos = NQ_*OUT_;
        const int off_bat = off_pos + NQ_*3;
        const int off_lf  = off_bat + NQ_;
        if (out_size >= off_lf + NQ_*9) {
            float* pos_out = outp + off_pos;
            float* bat_out = outp + off_bat;
            float* lf_out  = outp + off_lf;
            pos_out[qid*3+0] = p0; pos_out[qid*3+1] = p1; pos_out[qid*3+2] = p2;
            bat_out[qid] = (float)b;
#pragma unroll
            for (int i = 0; i < 9; i++) lf_out[qid*9+i] = r[i];
        }
    }
}

// ---------------------------------------------------------------------------
// Warp-distributed top-32 insert — redux.sync based (proven)
// ---------------------------------------------------------------------------
__device__ __forceinline__ void topk_insert(float d2, int gidx,
                                            uint32_t& kdk, int& ki, float& th, int lane)
{
    unsigned m = __ballot_sync(0xffffffffu, d2 < th);
    while (m) {
        int src = __ffs(m) - 1; m &= m - 1;
        float v  = __shfl_sync(0xffffffffu, d2,  src);
        int   vi = __shfl_sync(0xffffffffu, gidx, src);
        if (v < th) {
            uint32_t mx = redux_max_(kdk);
            unsigned vict = __ballot_sync(0xffffffffu, kdk == mx);
            int ml = __ffs(vict) - 1;
            if (lane == ml) { kdk = fkey_(v); ki = vi; }
            th = funkey_(redux_max_(kdk));
        }
    }
}

// ---------------------------------------------------------------------------
// Kernel 2: int8 dp4a screening KNN (R14 math, 256-key buffered tiles ->
// half the barriers). Warp owns 8 queries.
// ---------------------------------------------------------------------------
__global__ void __launch_bounds__(256) k_knn_i8()
{
    extern __shared__ uint32_t sh[];
    uint32_t* skq  = sh;                               // [QB_][20]
    uint32_t* skey = sh + QB_*ROWQ_;                   // [2][TK2_][20]
    float*    skn  = (float*)(sh + QB_*ROWQ_ + 2*TK2_*ROWQ_);           // [2][TK2_]
    float*    ssc  = (float*)(sh + QB_*ROWQ_ + 2*TK2_*ROWQ_ + 2*TK2_);  // [2][TK2_]

    const int tid = threadIdx.x, lane = tid & 31, w = tid >> 5;
    const int qbase = blockIdx.x * QB_;
    const int b = qbase >> 12;
    const int kb0 = b * N_;

    // stage 64 query rows
    for (int i = tid; i < QB_*5; i += 256) {
        int row = i / 5, g = i - row*5;
        int pt = kb0 + ((qbase + row) - b*M_) * STRIDE_;
        *(uint4*)(skq + row*ROWQ_ + 4*g) = *(const uint4*)(g_kfq + (size_t)pt*ROWQ_ + 4*g);
    }
    // stage tile 0 (256 keys)
    for (int i = tid; i < TK2_*5; i += 256) {
        int row = i / 5, g = i - row*5;
        *(uint4*)(skey + row*ROWQ_ + 4*g) = *(const uint4*)(g_kfq + (size_t)(kb0 + row)*ROWQ_ + 4*g);
    }
    for (int i = tid; i < TK2_; i += 256) { skn[i] = g_kn[kb0 + i]; ssc[i] = g_ksc[kb0 + i]; }

    float sq[8];
#pragma unroll
    for (int j = 0; j < 8; j++)
        sq[j] = g_ksc[kb0 + ((qbase + w*8 + j) - b*M_) * STRIDE_];

    uint32_t kdk[8];
    float th[8];
    int   ki[8];
    const uint32_t KINF = fkey_(CUDART_INF_F);
#pragma unroll
    for (int j = 0; j < 8; j++) { kdk[j] = KINF; ki[j] = 0; th[j] = CUDART_INF_F; }
    const uint32_t* qb = skq + (w*8)*ROWQ_;

    __syncthreads();

    for (int t = 0; t < NT2_; t++) {
        const int buf = t & 1;
        // prefetch next 256-key tile into other buffer
        if (t + 1 < NT2_) {
            uint32_t* dst = skey + (buf^1)*TK2_*ROWQ_;
            const uint32_t* src = g_kfq + (size_t)(kb0 + (t+1)*TK2_)*ROWQ_;
            for (int i = tid; i < TK2_*5; i += 256) {
                int row = i / 5, g = i - row*5;
                *(uint4*)(dst + row*ROWQ_ + 4*g) = *(const uint4*)(src + (size_t)row*ROWQ_ + 4*g);
            }
            for (int i = tid; i < TK2_; i += 256) {
                skn[(buf^1)*TK2_ + i] = g_kn[kb0 + (t+1)*TK2_ + i];
                ssc[(buf^1)*TK2_ + i] = g_ksc[kb0 + (t+1)*TK2_ + i];
            }
        }

        const uint32_t* kbb = skey + buf*TK2_*ROWQ_;
#pragma unroll 1
        for (int half = 0; half < 2; half++) {
            const uint32_t* kb = kbb + (half*128)*ROWQ_;
            int acc[8][4];
#pragma unroll
            for (int q = 0; q < 8; q++) { acc[q][0]=0; acc[q][1]=0; acc[q][2]=0; acc[q][3]=0; }

#pragma unroll
            for (int g = 0; g < 5; g++) {
                uint4 k0 = *(const uint4*)(kb + (lane     )*ROWQ_ + 4*g);
                uint4 k1 = *(const uint4*)(kb + (lane + 32)*ROWQ_ + 4*g);
                uint4 k2 = *(const uint4*)(kb + (lane + 64)*ROWQ_ + 4*g);
                uint4 k3 = *(const uint4*)(kb + (lane + 96)*ROWQ_ + 4*g);
#pragma unroll
                for (int q = 0; q < 8; q++) {
                    uint4 qv = *(const uint4*)(qb + q*ROWQ_ + 4*g);   // broadcast LDS.128
                    acc[q][0] = __dp4a((int)qv.x, (int)k0.x, acc[q][0]);
                    acc[q][1] = __dp4a((int)qv.x, (int)k1.x, acc[q][1]);
                    acc[q][2] = __dp4a((int)qv.x, (int)k2.x, acc[q][2]);
                    acc[q][3] = __dp4a((int)qv.x, (int)k3.x, acc[q][3]);
                    acc[q][0] = __dp4a((int)qv.y, (int)k0.y, acc[q][0]);
                    acc[q][1] = __dp4a((int)qv.y, (int)k1.y, acc[q][1]);
                    acc[q][2] = __dp4a((int)qv.y, (int)k2.y, acc[q][2]);
                    acc[q][3] = __dp4a((int)qv.y, (int)k3.y, acc[q][3]);
                    acc[q][0] = __dp4a((int)qv.z, (int)k0.z, acc[q][0]);
                    acc[q][1] = __dp4a((int)qv.z, (int)k1.z, acc[q][1]);
                    acc[q][2] = __dp4a((int)qv.z, (int)k2.z, acc[q][2]);
                    acc[q][3] = __dp4a((int)qv.z, (int)k3.z, acc[q][3]);
                    acc[q][0] = __dp4a((int)qv.w, (int)k0.w, acc[q][0]);
                    acc[q][1] = __dp4a((int)qv.w, (int)k1.w, acc[q][1]);
                    acc[q][2] = __dp4a((int)qv.w, (int)k2.w, acc[q][2]);
                    acc[q][3] = __dp4a((int)qv.w, (int)k3.w, acc[q][3]);
                }
            }

            const float* knb = skn + buf*TK2_ + half*128;
            const float* scb = ssc + buf*TK2_ + half*128;
            const float kn0 = knb[lane], kn1 = knb[lane+32], kn2 = knb[lane+64], kn3 = knb[lane+96];
            const float c0 = -2.f*scb[lane],    c1 = -2.f*scb[lane+32];
            const float c2 = -2.f*scb[lane+64], c3 = -2.f*scb[lane+96];
            const int gi = kb0 + t*TK2_ + half*128 + lane;
#pragma unroll
            for (int q = 0; q < 8; q++) {
                float d20 = fmaf((float)acc[q][0], sq[q]*c0, kn0);
                float d21 = fmaf((float)acc[q][1], sq[q]*c1, kn1);
                float d22 = fmaf((float)acc[q][2], sq[q]*c2, kn2);
                float d23 = fmaf((float)acc[q][3], sq[q]*c3, kn3);
                float mn = fminf(fminf(d20, d21), fminf(d22, d23));
                if (__ballot_sync(0xffffffffu, mn < th[q])) {
                    topk_insert(d20, gi,    kdk[q], ki[q], th[q], lane);
                    topk_insert(d21, gi+32, kdk[q], ki[q], th[q], lane);
                    topk_insert(d22, gi+64, kdk[q], ki[q], th[q], lane);
                    topk_insert(d23, gi+96, kdk[q], ki[q], th[q], lane);
                }
            }
        }
        __syncthreads();
    }

#pragma unroll
    for (int q = 0; q < 8; q++)
        g_cand[(size_t)(qbase + w*8 + q)*K2_ + lane] = ki[q];
}

// ---------------------------------------------------------------------------
// Kernel 2b: exact fp32 re-rank of 32 candidates -> top-20 set.
// ---------------------------------------------------------------------------
__global__ void __launch_bounds__(256) k_rerank()
{
    const int tid = threadIdx.x, lane = tid & 31, w = tid >> 5;
    const int q = blockIdx.x * 8 + w;
    const int b = q >> 12;
    const int pt = b*N_ + (q - b*M_) * STRIDE_;

    const int cand = g_cand[(size_t)q*K2_ + lane];
    const float4* qr = (const float4*)(g_kf + (size_t)pt*KFS_);
    const float4* kr = (const float4*)(g_kf + (size_t)cand*KFS_);
    float dot = 0.f;
#pragma unroll
    for (int g = 0; g < 17; g++) {
        float4 a = qr[g], c = kr[g];
        dot = fmaf(a.x,c.x, fmaf(a.y,c.y, fmaf(a.z,c.z, fmaf(a.w,c.w, dot))));
    }
    float d2 = g_kn[cand] - 2.f*dot;

#pragma unroll
    for (int r = 0; r < K_; r++) {
        float mv = d2; int ml = lane;
#pragma unroll
        for (int off = 16; off; off >>= 1) {
            float om = __shfl_xor_sync(0xffffffffu, mv, off);
            int   ol = __shfl_xor_sync(0xffffffffu, ml, off);
            if (om < mv || (om == mv && ol < ml)) { mv = om; ml = ol; }
        }
        if (lane == ml) { g_nbr[q*K_ + r] = cand; d2 = CUDART_INF_F; }
    }
}

// ---------------------------------------------------------------------------
// Kernel 3: edge MLP + maxpool — 2 groups x 10 edges (exact 20, no dups),
// weights staged in registers per 4-row chunk. Block = 128 thr = 4 warps.
// ---------------------------------------------------------------------------
__global__ void __launch_bounds__(128, 4) k_mlp(const float* __restrict__ x,
                                                const float* __restrict__ lfr,
                                                const float* __restrict__ W1,
                                                const float* __restrict__ b1,
                                                const float* __restrict__ W2,
                                                const float* __restrict__ b2,
                                                float* __restrict__ outp)
{
    __shared__ __align__(16) float sxd[4][D_];
    __shared__ float slf[4][12];
    __shared__ __align__(16) float srel[4][10][D_];
    __shared__ __align__(16) float srl[4][10][D_];
    __shared__ __align__(16) float sa1[4][10][HID_];

    const int tid = threadIdx.x, lane = tid & 31, w = tid >> 5;
    const int q  = blockIdx.x * 4 + w;
    const int b  = q >> 12;
    const int pt = b*N_ + (q - b*M_) * STRIDE_;

    for (int d = lane; d < D_; d += 32) sxd[w][d] = x[(size_t)pt*D_ + d];
    if (lane < 9) slf[w][lane] = lfr[(size_t)pt*9 + lane];
    __syncwarp();

    const int c4 = lane * 4;
    float4 base = *(const float4*)(b1 + c4);
#pragma unroll 8
    for (int d = 0; d < D_; d++) {
        float xv = sxd[w][d];
        float4 w4 = __ldg((const float4*)(W1 + d*HID_ + c4));
        base.x += xv*w4.x; base.y += xv*w4.y; base.z += xv*w4.z; base.w += xv*w4.w;
    }
    const float4 b2v = __ldg((const float4*)(b2 + c4));
    float4 mx = make_float4(-CUDART_INF_F, -CUDART_INF_F, -CUDART_INF_F, -CUDART_INF_F);

    for (int grp = 0; grp < 2; grp++) {
        __syncwarp();
        int s = 0;
        if (lane < 10) s = g_nbr[q*K_ + grp*10 + lane];
        int ss[10];
#pragma unroll
        for (int e = 0; e < 10; e++) ss[e] = __shfl_sync(0xffffffffu, s, e);

#pragma unroll
        for (int e = 0; e < 10; e++) {
            const float* xs = x + (size_t)ss[e] * D_;
#pragma unroll
            for (int d = lane; d < D_; d += 32)
                srel[w][e][d] = xs[d] - sxd[w][d];
        }
        __syncwarp();
        // rotate rel -> rel_local with R = lf_dst (10 edges x 64 dims = 20 items/lane)
#pragma unroll
        for (int t = 0; t < 20; t++) {
            int item = lane + 32*t;
            int e = item >> 6;
            int d = item & 63;
            float v;
            if (d < 16) v = srel[w][e][d];
            else {
                int dd = d - 16;
                int a  = dd % 3;
                int vb = 16 + dd - a;
                v = slf[w][a*3+0]*srel[w][e][vb]
                  + slf[w][a*3+1]*srel[w][e][vb+1]
                  + slf[w][a*3+2]*srel[w][e][vb+2];
            }
            srl[w][e][d] = v;
        }
        __syncwarp();

        // layer 1 (bottom half of W1): stage 4 weight rows in regs, 10 edges each
        float4 ac[10];
#pragma unroll
        for (int e = 0; e < 10; e++) ac[e] = make_float4(0.f, 0.f, 0.f, 0.f);
#pragma unroll 1
        for (int d = 0; d < D_; d += 4) {
            float4 w0 = __ldg((const float4*)(W1 + (D_+d+0)*HID_ + c4));
            float4 w1 = __ldg((const float4*)(W1 + (D_+d+1)*HID_ + c4));
            float4 w2 = __ldg((const float4*)(W1 + (D_+d+2)*HID_ + c4));
            float4 w3 = __ldg((const float4*)(W1 + (D_+d+3)*HID_ + c4));
#pragma unroll
            for (int e = 0; e < 10; e++) {
                float4 rv = *(const float4*)&srl[w][e][d];
                ac[e].x += rv.x*w0.x + rv.y*w1.x + rv.z*w2.x + rv.w*w3.x;
                ac[e].y += rv.x*w0.y + rv.y*w1.y + rv.z*w2.y + rv.w*w3.y;
                ac[e].z += rv.x*w0.z + rv.y*w1.z + rv.z*w2.z + rv.w*w3.z;
                ac[e].w += rv.x*w0.w + rv.y*w1.w + rv.z*w2.w + rv.w*w3.w;
            }
        }
#pragma unroll
        for (int e = 0; e < 10; e++) {
            float4 a;
            a.x = fmaxf(base.x + ac[e].x, 0.f);
            a.y = fmaxf(base.y + ac[e].y, 0.f);
            a.z = fmaxf(base.z + ac[e].z, 0.f);
            a.w = fmaxf(base.w + ac[e].w, 0.f);
            *(float4*)&sa1[w][e][c4] = a;
        }
        __syncwarp();

        // layer 2: stage 4 weight rows in regs, 10 edges each
        float4 m[10];
#pragma unroll
        for (int e = 0; e < 10; e++) m[e] = b2v;
#pragma unroll 1
        for (int j = 0; j < HID_; j += 4) {
            float4 w0 = __ldg((const float4*)(W2 + (j+0)*HID_ + c4));
            float4 w1 = __ldg((const float4*)(W2 + (j+1)*HID_ + c4));
            float4 w2 = __ldg((const float4*)(W2 + (j+2)*HID_ + c4));
            float4 w3 = __ldg((const float4*)(W2 + (j+3)*HID_ + c4));
#pragma unroll
            for (int e = 0; e < 10; e++) {
                float4 av = *(const float4*)&sa1[w][e][j];
                m[e].x += av.x*w0.x + av.y*w1.x + av.z*w2.x + av.w*w3.x;
                m[e].y += av.x*w0.y + av.y*w1.y + av.z*w2.y + av.w*w3.y;
                m[e].z += av.x*w0.z + av.y*w1.z + av.z*w2.z + av.w*w3.z;
                m[e].w += av.x*w0.w + av.y*w1.w + av.z*w2.w + av.w*w3.w;
            }
        }
#pragma unroll
        for (int e = 0; e < 10; e++) {
            mx.x = fmaxf(mx.x, m[e].x);
            mx.y = fmaxf(mx.y, m[e].y);
            mx.z = fmaxf(mx.z, m[e].z);
            mx.w = fmaxf(mx.w, m[e].w);
        }
    }

    *(float4*)(outp + (size_t)q*OUT_ + c4) = mx;
}

// ---------------------------------------------------------------------------
extern "C" void kernel_launch(void* const* d_in, const int* in_sizes, int n_in,
                              void* d_out, int out_size)
{
    const float* x   = (const float*)d_in[0];
    const float* pos = (const float*)d_in[1];
    const float* lfr = (const float*)d_in[2];
    const float* W1  = (const float*)d_in[4];
    const float* b1  = (const float*)d_in[5];
    const float* W2  = (const float*)d_in[6];
    const float* b2  = (const float*)d_in[7];
    float* outp = (float*)d_out;

    const int knn_smem = (QB_*ROWQ_ + 2*TK2_*ROWQ_ + 2*TK2_ + 2*TK2_) * 4; // 50176 B
    cudaFuncSetAttribute(k_knn_i8, cudaFuncAttributeMaxDynamicSharedMemorySize, knn_smem);

    k_prep<<<(B_*N_ + 255)/256, 256>>>(x, pos, lfr, outp, out_size);
    k_knn_i8<<<NQ_/QB_, 256, knn_smem>>>();
    k_rerank<<<NQ_/8, 256>>>();
    k_mlp<<<NQ_/4, 128>>>(x, lfr, W1, b1, W2, b2, outp);
}